// round 1
// baseline (speedup 1.0000x reference)
#include <cuda_runtime.h>
#include <math.h>

// ---- problem constants ----
#define NB 4
#define NT 12
#define NV 512
#define NC 64
#define ND 8     // pos-emb dim
#define NTS 3
#define NP 12
#define NL 4
#define NM (NTS*NV)   // 1536  (K of big GEMM)
#define NN (NT*NC)    // 768   (N of big GEMM)

// ---- scratch (device globals; no allocation) ----
__device__ float g_h[NB*NT*NV*NC];        // current layer features (B,T,V,C)
__device__ float g_u[NB*NV*NN];           // GEMM output u[b][j][t*64+c]
__device__ float g_EbT[NV*NV];            // exp(base) transposed: [j][i]
__device__ float g_gs0[NV];
__device__ float g_gs1[NV];
__device__ float g_ept[NB*NT*NTS];
__device__ float g_skips[NB*NV*4*NC];     // [b][v][256]
__device__ float g_fswT[NL*NN*NC];        // fs_w transposed: [l][(c*12+t)][oo]
__device__ float g_g1wT[NL*NC*2*NC];      // glu1_w transposed: [l][c][o]
__device__ float g_goutT[256*512];        // gout_w transposed: [c][o]
__device__ float g_outT[256*NP];          // out_w transposed: [c][p]

__device__ __forceinline__ float sigm(float x) { return 1.0f/(1.0f+expf(-x)); }

// ---- one-time weight transposes ----
__global__ void k_transw(const float* __restrict__ fs_w, const float* __restrict__ g1w,
                         const float* __restrict__ gout_w, const float* __restrict__ out_w) {
    int idx = blockIdx.x*256 + threadIdx.x;
    if (idx < NL*NN*NC) {                       // 196608
        int l = idx / (NN*NC); int r = idx % (NN*NC); int ct = r >> 6; int oo = r & 63;
        g_fswT[idx] = fs_w[l*NC*NN + oo*NN + ct];
        return;
    }
    idx -= NL*NN*NC;
    if (idx < NL*NC*2*NC) {                     // 32768
        int l = idx / (NC*2*NC); int r = idx % (NC*2*NC); int c = r >> 7; int o = r & 127;
        g_g1wT[idx] = g1w[l*2*NC*NC + o*NC + c];
        return;
    }
    idx -= NL*NC*2*NC;
    if (idx < 256*512) {                        // 131072
        int c = idx >> 9; int o = idx & 511;
        g_goutT[idx] = gout_w[o*256 + c];
        return;
    }
    idx -= 256*512;
    if (idx < 256*NP) {                         // 3072
        int c = idx / NP; int p = idx % NP;
        g_outT[idx] = out_w[p*256 + c];
    }
}

// ---- input layer: h = x*Wi + bi (D=1) ----
__global__ void k_input(const float* __restrict__ x, const float* __restrict__ Wi,
                        const float* __restrict__ bi) {
    int idx = blockIdx.x*256 + threadIdx.x;   // over B*T*V*C
    int c = idx & 63;
    int r = idx >> 6;
    g_h[idx] = x[r]*Wi[c] + bi[c];
}

// ---- per-layer small precompute: gs0, gs1, ept ----
__global__ void k_prep(const float* __restrict__ sape, const float* __restrict__ tape,
                       const float* __restrict__ trpe, const float* __restrict__ gc_mu,
                       const float* __restrict__ gc_sig, int l) {
    const float* mu = gc_mu + l*6*ND;
    const float* sg = gc_sig + l*6*ND;
    __shared__ float gt2[NB*NT];
    __shared__ float gt3[NB*(NT+2)];
    __shared__ float gt5[NTS];
    int tid = threadIdx.x;  // 512
    if (tid < NV) {
        float a0 = 0.f, a1 = 0.f;
        #pragma unroll
        for (int dd = 0; dd < ND; dd++) {
            float e = sape[tid*ND + dd];
            float d0 = e - mu[0*ND+dd], d1 = e - mu[1*ND+dd];
            a0 += -0.5f*d0*d0*sg[0*ND+dd]*sg[0*ND+dd];
            a1 += -0.5f*d1*d1*sg[1*ND+dd]*sg[1*ND+dd];
        }
        g_gs0[tid] = a0; g_gs1[tid] = a1;
    }
    if (tid < NB*NT) {
        float a = 0.f;
        #pragma unroll
        for (int dd = 0; dd < ND; dd++) {
            float e = tape[tid*ND + dd]; float dv = e - mu[2*ND+dd];
            a += -0.5f*dv*dv*sg[2*ND+dd]*sg[2*ND+dd];
        }
        gt2[tid] = a;
    }
    if (tid < NB*(NT+2)) {
        int b = tid/(NT+2), tau = tid%(NT+2);
        float a = 0.f;
        #pragma unroll
        for (int dd = 0; dd < ND; dd++) {
            float e = (tau < 2) ? 0.0f : tape[(b*NT + (tau-2))*ND + dd];
            float dv = e - mu[3*ND+dd];
            a += -0.5f*dv*dv*sg[3*ND+dd]*sg[3*ND+dd];
        }
        gt3[tid] = a;
    }
    if (tid < NTS) {
        float a = 0.f;
        #pragma unroll
        for (int dd = 0; dd < ND; dd++) {
            float e = trpe[tid*ND + dd]; float dv = e - mu[5*ND+dd];
            a += -0.5f*dv*dv*sg[5*ND+dd]*sg[5*ND+dd];
        }
        gt5[tid] = a;
    }
    __syncthreads();
    if (tid < NB*NT*NTS) {
        int k = tid % NTS; int bt = tid / NTS;
        int b = bt / NT, t = bt % NT;
        g_ept[tid] = expf(gt2[bt] + gt3[b*(NT+2) + t + k] + gt5[k]);
    }
}

// ---- Ebase^T[j][i] = exp(gs0[i]+gs1[j]+gc(srpe[i,j],4)) ----
__global__ void k_ebase(const float* __restrict__ srpe, const float* __restrict__ gc_mu,
                        const float* __restrict__ gc_sig, int l) {
    int idx = blockIdx.x*256 + threadIdx.x;   // i*V + j (coalesced srpe reads)
    int i = idx >> 9, j = idx & 511;
    const float* mu = gc_mu + l*48 + 32;
    const float* sg = gc_sig + l*48 + 32;
    const float* e = srpe + (size_t)idx*ND;
    float a = 0.f;
    #pragma unroll
    for (int dd = 0; dd < ND; dd++) {
        float dv = e[dd] - mu[dd];
        a += -0.5f*dv*dv*sg[dd]*sg[dd];
    }
    g_EbT[j*NV + i] = expf(a + g_gs0[i] + g_gs1[j]);
}

// ---- big fused GEMM: u[b][j][t*64+c] = sum_m (mask*EbT)[j,m] * (ept*hpad)[m,(t,c)] ----
#define BM 128
#define BN 64
#define BK 16
__global__ void __launch_bounds__(128) k_gemm(const float* __restrict__ mask) {
    int b  = blockIdx.z;
    int t  = blockIdx.x;             // BN=64 == one timestep per N tile
    int m0 = blockIdx.y * BM;
    __shared__ float As[BK][BM];
    __shared__ float Bs[BK][BN];
    int tid = threadIdx.x;
    int tx = tid & 7;                // 0..7  (TN=8)
    int ty = tid >> 3;               // 0..15 (TM=8)
    float acc[8][8] = {};

    float eptv[NTS];
    const float* hbase[NTS];
    #pragma unroll
    for (int k = 0; k < NTS; k++) {
        int tt = t + k - 2;
        eptv[k]  = (tt >= 0) ? g_ept[(b*NT + t)*NTS + k] : 0.0f;
        hbase[k] = (tt >= 0) ? (g_h + (size_t)((b*NT + tt)*NV)*NC) : g_h;  // dummy (x0)
    }
    const float* maskb = mask + (size_t)b*NV*NM;

    for (int k0 = 0; k0 < NM; k0 += BK) {
        int kw = k0 >> 9;            // window index (const over tile)
        int i0 = k0 & 511;
        // A tile: mask * EbT (128 x 16), 4 float4 per thread, transposed store
        #pragma unroll
        for (int s = 0; s < 4; s++) {
            int cidx = tid + s*128;
            int row  = cidx >> 2;
            int c4   = cidx & 3;
            int j    = m0 + row;
            float4 mv = *reinterpret_cast<const float4*>(maskb + (size_t)j*NM + k0 + c4*4);
            float4 ev = *reinterpret_cast<const float4*>(g_EbT + j*NV + i0 + c4*4);
            As[c4*4+0][row] = mv.x*ev.x;
            As[c4*4+1][row] = mv.y*ev.y;
            As[c4*4+2][row] = mv.z*ev.z;
            As[c4*4+3][row] = mv.w*ev.w;
        }
        // B tile: ept * h (16 x 64), 2 float4 per thread
        {
            float e = eptv[kw];
            const float* hb = hbase[kw];
            #pragma unroll
            for (int s = 0; s < 2; s++) {
                int cidx = tid + s*128;
                int row  = cidx >> 4;     // 0..15
                int c4   = cidx & 15;
                int i    = i0 + row;
                float4 hv = *reinterpret_cast<const float4*>(hb + (size_t)i*NC + c4*4);
                *reinterpret_cast<float4*>(&Bs[row][c4*4]) =
                    make_float4(e*hv.x, e*hv.y, e*hv.z, e*hv.w);
            }
        }
        __syncthreads();
        #pragma unroll
        for (int kk = 0; kk < BK; kk++) {
            float4 a0 = *reinterpret_cast<const float4*>(&As[kk][ty*8]);
            float4 a1 = *reinterpret_cast<const float4*>(&As[kk][ty*8+4]);
            float4 b0 = *reinterpret_cast<const float4*>(&Bs[kk][tx*8]);
            float4 b1 = *reinterpret_cast<const float4*>(&Bs[kk][tx*8+4]);
            float av[8] = {a0.x,a0.y,a0.z,a0.w,a1.x,a1.y,a1.z,a1.w};
            float bv[8] = {b0.x,b0.y,b0.z,b0.w,b1.x,b1.y,b1.z,b1.w};
            #pragma unroll
            for (int q = 0; q < 8; q++)
                #pragma unroll
                for (int r = 0; r < 8; r++)
                    acc[q][r] += av[q]*bv[r];
        }
        __syncthreads();
    }
    #pragma unroll
    for (int q = 0; q < 8; q++) {
        float* dst = g_u + (size_t)(b*NV + m0 + ty*8 + q)*NN + t*NC + tx*8;
        *reinterpret_cast<float4*>(dst)   = make_float4(acc[q][0],acc[q][1],acc[q][2],acc[q][3]);
        *reinterpret_cast<float4*>(dst+4) = make_float4(acc[q][4],acc[q][5],acc[q][6],acc[q][7]);
    }
}

// ---- gate: g = u@Wg + bg + sape@Wsp + tape@Wtp ; h = gl*sigmoid(gr) ----
__global__ void __launch_bounds__(128) k_gate(const float* __restrict__ sape,
                                              const float* __restrict__ tape,
                                              const float* __restrict__ Wg,
                                              const float* __restrict__ bg,
                                              const float* __restrict__ Wsp,
                                              const float* __restrict__ Wtp, int l) {
    int rid = blockIdx.x;             // over B*T*V
    int j  = rid & 511;
    int bt = rid >> 9;
    int t = bt % NT, b = bt / NT;
    __shared__ float ush[NC];
    __shared__ float gsh[2*NC];
    int o = threadIdx.x;              // 128
    if (o < NC) ush[o] = g_u[(size_t)(b*NV + j)*NN + t*NC + o];
    __syncthreads();
    const float* wg  = Wg  + l*NC*2*NC;
    const float* wsp = Wsp + l*ND*2*NC;
    const float* wtp = Wtp + l*ND*2*NC;
    float acc = bg[l*2*NC + o];
    #pragma unroll
    for (int dd = 0; dd < ND; dd++)
        acc += sape[j*ND+dd]*wsp[dd*128+o] + tape[(b*NT+t)*ND+dd]*wtp[dd*128+o];
    #pragma unroll 8
    for (int c = 0; c < NC; c++) acc += ush[c]*wg[c*128 + o];
    gsh[o] = acc;
    __syncthreads();
    if (o < NC) {
        g_h[(size_t)((b*NT+t)*NV + j)*NC + o] = gsh[o] * sigm(gsh[o+NC]);
    }
}

// ---- GFS (time conv) + GLU1 -> skips, 8 nodes per block ----
__global__ void __launch_bounds__(128) k_gfs(const float* __restrict__ fs_b,
                                             const float* __restrict__ g1b, int l) {
    int b  = blockIdx.x >> 6;
    int v0 = (blockIdx.x & 63) << 3;
    __shared__ float hs[8][NN];        // 24KB
    __shared__ float red[2][NC][8];
    __shared__ float ysh[8][NC];
    __shared__ float zsh[8][2*NC];
    int tid = threadIdx.x;             // 128
    for (int idx = tid; idx < 8*NN; idx += 128) {
        int vv = idx / NN; int tc = idx % NN;
        int t = tc >> 6, c = tc & 63;
        hs[vv][tc] = g_h[(size_t)((b*NT+t)*NV + v0+vv)*NC + c];
    }
    __syncthreads();
    int oo = tid & 63, half = tid >> 6;
    const float* fwT = g_fswT + l*NN*NC;
    float part[8] = {};
    for (int c = half*32; c < half*32 + 32; c++) {
        #pragma unroll
        for (int t = 0; t < NT; t++) {
            float w = fwT[(c*NT + t)*NC + oo];
            #pragma unroll
            for (int vv = 0; vv < 8; vv++) part[vv] += hs[vv][t*NC + c]*w;
        }
    }
    #pragma unroll
    for (int vv = 0; vv < 8; vv++) red[half][oo][vv] = part[vv];
    __syncthreads();
    if (half == 0) {
        float fb = fs_b[l*NC + oo];
        #pragma unroll
        for (int vv = 0; vv < 8; vv++) ysh[vv][oo] = red[0][oo][vv] + red[1][oo][vv] + fb;
    }
    __syncthreads();
    const float* gT = g_g1wT + l*NC*2*NC;
    float zacc[8];
    float zb = g1b[l*2*NC + tid];
    #pragma unroll
    for (int vv = 0; vv < 8; vv++) zacc[vv] = zb;
    for (int c = 0; c < NC; c++) {
        float w = gT[c*128 + tid];
        #pragma unroll
        for (int vv = 0; vv < 8; vv++) zacc[vv] += ysh[vv][c]*w;
    }
    #pragma unroll
    for (int vv = 0; vv < 8; vv++) zsh[vv][tid] = zacc[vv];
    __syncthreads();
    if (tid < NC) {
        #pragma unroll
        for (int vv = 0; vv < 8; vv++) {
            float zl = zsh[vv][tid], zr = zsh[vv][tid+NC];
            g_skips[(size_t)(b*NV + v0+vv)*256 + l*NC + tid] = zl * sigm(zr);
        }
    }
}

// ---- output GLU + head, 16 nodes per block ----
__global__ void __launch_bounds__(256) k_out(const float* __restrict__ gout_b,
                                             const float* __restrict__ out_b,
                                             float* __restrict__ out) {
    int b  = blockIdx.x >> 5;
    int v0 = (blockIdx.x & 31) << 4;
    __shared__ float sin_[256][16];
    __shared__ float ssh[256][16];
    int tid = threadIdx.x;             // 256
    for (int idx = tid; idx < 256*16; idx += 256) {
        int vv = idx >> 8, ch = idx & 255;
        sin_[ch][vv] = g_skips[(size_t)(b*NV + v0+vv)*256 + ch];
    }
    __syncthreads();
    int o = tid;
    float a0[16] = {}, a1[16] = {};
    for (int c = 0; c < 256; c++) {
        float w0 = g_goutT[c*512 + o];
        float w1 = g_goutT[c*512 + o + 256];
        #pragma unroll
        for (int vv = 0; vv < 16; vv++) {
            float s = sin_[c][vv];
            a0[vv] += w0*s; a1[vv] += w1*s;
        }
    }
    float b0 = gout_b[o], b1 = gout_b[o+256];
    #pragma unroll
    for (int vv = 0; vv < 16; vv++) ssh[o][vv] = (a0[vv]+b0) * sigm(a1[vv]+b1);
    __syncthreads();
    if (tid < NP*16) {
        int p = tid >> 4, vv = tid & 15;
        float a = out_b[p];
        for (int c = 0; c < 256; c++) a += ssh[c][vv]*g_outT[c*NP + p];
        out[(b*NP + p)*NV + v0 + vv] = a;
    }
}

extern "C" void kernel_launch(void* const* d_in, const int* in_sizes, int n_in,
                              void* d_out, int out_size) {
    const float* x      = (const float*)d_in[0];
    const float* sape   = (const float*)d_in[1];
    const float* tape   = (const float*)d_in[2];
    const float* srpe   = (const float*)d_in[3];
    const float* trpe   = (const float*)d_in[4];
    // d_in[5]=zeros_x, d_in[6]=zeros_tape: unused (padding handled analytically)
    const float* mask   = (const float*)d_in[7];
    const float* Wi     = (const float*)d_in[8];
    const float* bi     = (const float*)d_in[9];
    const float* gc_mu  = (const float*)d_in[10];
    const float* gc_sig = (const float*)d_in[11];
    const float* Wg     = (const float*)d_in[12];
    const float* bg     = (const float*)d_in[13];
    const float* Wsp    = (const float*)d_in[14];
    const float* Wtp    = (const float*)d_in[15];
    const float* fs_w   = (const float*)d_in[16];
    const float* fs_b   = (const float*)d_in[17];
    const float* g1w    = (const float*)d_in[18];
    const float* g1b    = (const float*)d_in[19];
    const float* goutw  = (const float*)d_in[20];
    const float* goutb  = (const float*)d_in[21];
    const float* outw   = (const float*)d_in[22];
    const float* outb   = (const float*)d_in[23];
    float* out = (float*)d_out;

    k_transw<<<1420, 256>>>(fs_w, g1w, goutw, outw);
    k_input<<<6144, 256>>>(x, Wi, bi);
    for (int l = 0; l < NL; l++) {
        k_prep<<<1, 512>>>(sape, tape, trpe, gc_mu, gc_sig, l);
        k_ebase<<<1024, 256>>>(srpe, gc_mu, gc_sig, l);
        dim3 gg(NN/BN, NV/BM, NB);   // (12, 4, 4)
        k_gemm<<<gg, 128>>>(mask);
        k_gate<<<NB*NT*NV, 128>>>(sape, tape, Wg, bg, Wsp, Wtp, l);
        k_gfs<<<NB*NV/8, 128>>>(fs_b, g1b, l);
    }
    k_out<<<NB*NV/16, 256>>>(goutb, outb, out);
}

// round 3
// speedup vs baseline: 1.1328x; 1.1328x over previous
#include <cuda_runtime.h>
#include <math.h>

// ---- problem constants ----
#define NB 4
#define NT 12
#define NV 512
#define NC 64
#define ND 8
#define NTS 3
#define NP 12
#define NL 4
#define NM (NTS*NV)   // 1536  (K of big GEMM)
#define NN (NT*NC)    // 768

// ---- scratch (device globals) ----
__device__ float g_hA[NB*NT*NV*NC];
__device__ float g_hB[NB*NT*NV*NC];
__device__ float g_EbT[NL*NV*NV];         // [l][j][i]
__device__ float g_gs0[NL*NV];
__device__ float g_gs1[NL*NV];
__device__ float g_ept[NL*NB*NT*NTS];
__device__ float g_skips[NB*NV*4*NC];
__device__ float g_fswT[NL*NN*NC];
__device__ float g_g1wT[NL*NC*2*NC];
__device__ float g_goutT[256*512];
__device__ float g_outT[256*NP];

__device__ __forceinline__ float sigm(float x) { return 1.0f/(1.0f+expf(-x)); }

// ---- one-time weight transposes ----
__global__ void k_transw(const float* __restrict__ fs_w, const float* __restrict__ g1w,
                         const float* __restrict__ gout_w, const float* __restrict__ out_w) {
    int idx = blockIdx.x*256 + threadIdx.x;
    if (idx < NL*NN*NC) {
        int l = idx / (NN*NC); int r = idx % (NN*NC); int ct = r >> 6; int oo = r & 63;
        g_fswT[idx] = fs_w[l*NC*NN + oo*NN + ct];
        return;
    }
    idx -= NL*NN*NC;
    if (idx < NL*NC*2*NC) {
        int l = idx / (NC*2*NC); int r = idx % (NC*2*NC); int c = r >> 7; int o = r & 127;
        g_g1wT[idx] = g1w[l*2*NC*NC + o*NC + c];
        return;
    }
    idx -= NL*NC*2*NC;
    if (idx < 256*512) {
        int c = idx >> 9; int o = idx & 511;
        g_goutT[idx] = gout_w[o*256 + c];
        return;
    }
    idx -= 256*512;
    if (idx < 256*NP) {
        int c = idx / NP; int p = idx % NP;
        g_outT[idx] = out_w[p*256 + c];
    }
}

// ---- input layer ----
__global__ void k_input(const float* __restrict__ x, const float* __restrict__ Wi,
                        const float* __restrict__ bi) {
    int idx = blockIdx.x*256 + threadIdx.x;
    int c = idx & 63;
    int r = idx >> 6;
    g_hA[idx] = x[r]*Wi[c] + bi[c];
}

// ---- per-layer small precompute (all layers at once, l = blockIdx.x) ----
__global__ void k_prep(const float* __restrict__ sape, const float* __restrict__ tape,
                       const float* __restrict__ trpe, const float* __restrict__ gc_mu,
                       const float* __restrict__ gc_sig) {
    int l = blockIdx.x;
    const float* mu = gc_mu + l*6*ND;
    const float* sg = gc_sig + l*6*ND;
    __shared__ float gt2[NB*NT];
    __shared__ float gt3[NB*(NT+2)];
    __shared__ float gt5[NTS];
    int tid = threadIdx.x;  // 512
    if (tid < NV) {
        float a0 = 0.f, a1 = 0.f;
        #pragma unroll
        for (int dd = 0; dd < ND; dd++) {
            float e = sape[tid*ND + dd];
            float d0 = e - mu[0*ND+dd], d1 = e - mu[1*ND+dd];
            a0 += -0.5f*d0*d0*sg[0*ND+dd]*sg[0*ND+dd];
            a1 += -0.5f*d1*d1*sg[1*ND+dd]*sg[1*ND+dd];
        }
        g_gs0[l*NV+tid] = a0; g_gs1[l*NV+tid] = a1;
    }
    if (tid < NB*NT) {
        float a = 0.f;
        #pragma unroll
        for (int dd = 0; dd < ND; dd++) {
            float e = tape[tid*ND + dd]; float dv = e - mu[2*ND+dd];
            a += -0.5f*dv*dv*sg[2*ND+dd]*sg[2*ND+dd];
        }
        gt2[tid] = a;
    }
    if (tid < NB*(NT+2)) {
        int b = tid/(NT+2), tau = tid%(NT+2);
        float a = 0.f;
        #pragma unroll
        for (int dd = 0; dd < ND; dd++) {
            float e = (tau < 2) ? 0.0f : tape[(b*NT + (tau-2))*ND + dd];
            float dv = e - mu[3*ND+dd];
            a += -0.5f*dv*dv*sg[3*ND+dd]*sg[3*ND+dd];
        }
        gt3[tid] = a;
    }
    if (tid < NTS) {
        float a = 0.f;
        #pragma unroll
        for (int dd = 0; dd < ND; dd++) {
            float e = trpe[tid*ND + dd]; float dv = e - mu[5*ND+dd];
            a += -0.5f*dv*dv*sg[5*ND+dd]*sg[5*ND+dd];
        }
        gt5[tid] = a;
    }
    __syncthreads();
    if (tid < NB*NT*NTS) {
        int k = tid % NTS; int bt = tid / NTS;
        int b = bt / NT, t = bt % NT;
        g_ept[l*NB*NT*NTS + tid] = expf(gt2[bt] + gt3[b*(NT+2) + t + k] + gt5[k]);
    }
}

// ---- Ebase^T for all layers: grid (1024, NL) ----
__global__ void k_ebase(const float* __restrict__ srpe, const float* __restrict__ gc_mu,
                        const float* __restrict__ gc_sig) {
    int l = blockIdx.y;
    int idx = blockIdx.x*256 + threadIdx.x;   // i*V + j
    int i = idx >> 9, j = idx & 511;
    const float* mu = gc_mu + l*48 + 32;
    const float* sg = gc_sig + l*48 + 32;
    const float* e = srpe + (size_t)idx*ND;
    float a = 0.f;
    #pragma unroll
    for (int dd = 0; dd < ND; dd++) {
        float dv = e[dd] - mu[dd];
        a += -0.5f*dv*dv*sg[dd]*sg[dd];
    }
    g_EbT[l*NV*NV + j*NV + i] = expf(a + g_gs0[l*NV+i] + g_gs1[l*NV+j]);
}

// ---- fused graph-conv GEMM + gate ----
// tile: BM=64 (j), BN=64 (one t), BK=16; 128 threads, 4x8 per thread.
// epilogue: g = u@Wg + sape@Wsp + tape@Wtp + bg; h = gl*sigm(gr)
#define BM 64
#define BN 64
#define BK 16
#define USW 73   // Us row width: 64 u cols + 8 sape cols + 1 pad
__global__ void __launch_bounds__(128) k_gconv(const float* __restrict__ mask,
                                               const float* __restrict__ sape,
                                               const float* __restrict__ tape,
                                               const float* __restrict__ Wg,
                                               const float* __restrict__ bg,
                                               const float* __restrict__ Wsp,
                                               const float* __restrict__ Wtp, int l) {
    const float* hin  = (l & 1) ? g_hB : g_hA;
    float*       hout = (l & 1) ? g_hA : g_hB;
    int b  = blockIdx.z;
    int t  = blockIdx.x;
    int m0 = blockIdx.y * BM;
    __shared__ __align__(16) float As[BM][BK+1];   // [m][k], pad -> conflict-free
    __shared__ __align__(16) float Bs[BK][BN];
    __shared__ __align__(16) float Us[BM][USW];    // u tile + 8 sape ext cols
    __shared__ __align__(16) float te_s[128];
    int tid = threadIdx.x;

    // per-block (b,t) bias vector: bg + tape@Wtp
    {
        int o = tid;
        float a = bg[l*128 + o];
        #pragma unroll
        for (int dd = 0; dd < ND; dd++)
            a += tape[(b*NT+t)*ND + dd] * Wtp[l*ND*128 + dd*128 + o];
        te_s[o] = a;
    }

    float eptv[NTS];
    const float* hb3[NTS];
    #pragma unroll
    for (int k = 0; k < NTS; k++) {
        int tt = t + k - 2;
        eptv[k] = (tt >= 0) ? g_ept[l*NB*NT*NTS + (b*NT + t)*NTS + k] : 0.0f;
        hb3[k]  = (tt >= 0) ? (hin + (size_t)((b*NT + tt)*NV)*NC) : hin;
    }
    const float* maskb = mask + (size_t)b*NV*NM;
    const float* ebl   = g_EbT + (size_t)l*NV*NV;

    int mt = tid >> 3;     // 0..15
    int nt = tid & 7;      // 0..7
    int m4 = mt * 4;
    float acc[4][8] = {};

    for (int k0 = 0; k0 < NM; k0 += BK) {
        int kw = k0 >> 9;
        int i0 = k0 & 511;
        // A tile 64x16: mask*EbT, [m][k] layout
        #pragma unroll
        for (int s = 0; s < 2; s++) {
            int cidx = tid + s*128;
            int row  = cidx >> 2;       // 0..63
            int c4   = cidx & 3;
            int j    = m0 + row;
            float4 mv = *reinterpret_cast<const float4*>(maskb + (size_t)j*NM + k0 + c4*4);
            float4 ev = *reinterpret_cast<const float4*>(ebl + j*NV + i0 + c4*4);
            As[row][c4*4+0] = mv.x*ev.x;
            As[row][c4*4+1] = mv.y*ev.y;
            As[row][c4*4+2] = mv.z*ev.z;
            As[row][c4*4+3] = mv.w*ev.w;
        }
        // B tile 16x64: ept*h
        {
            float e = eptv[kw];
            const float* hb = hb3[kw];
            #pragma unroll
            for (int s = 0; s < 2; s++) {
                int cidx = tid + s*128;
                int row  = cidx >> 4;   // 0..15
                int c4   = cidx & 15;
                float4 hv = *reinterpret_cast<const float4*>(hb + (size_t)(i0+row)*NC + c4*4);
                *reinterpret_cast<float4*>(&Bs[row][c4*4]) =
                    make_float4(e*hv.x, e*hv.y, e*hv.z, e*hv.w);
            }
        }
        __syncthreads();
        #pragma unroll
        for (int kk = 0; kk < BK; kk++) {
            float a0 = As[m4+0][kk], a1 = As[m4+1][kk],
                  a2 = As[m4+2][kk], a3 = As[m4+3][kk];
            float4 b0 = *reinterpret_cast<const float4*>(&Bs[kk][nt*8]);
            float4 b1 = *reinterpret_cast<const float4*>(&Bs[kk][nt*8+4]);
            float bv[8] = {b0.x,b0.y,b0.z,b0.w,b1.x,b1.y,b1.z,b1.w};
            #pragma unroll
            for (int r = 0; r < 8; r++) {
                acc[0][r] += a0*bv[r];
                acc[1][r] += a1*bv[r];
                acc[2][r] += a2*bv[r];
                acc[3][r] += a3*bv[r];
            }
        }
        __syncthreads();
    }

    // stage u tile (+ sape extension columns) in smem
    #pragma unroll
    for (int q = 0; q < 4; q++)
        #pragma unroll
        for (int r = 0; r < 8; r++)
            Us[m4+q][nt*8+r] = acc[q][r];
    #pragma unroll
    for (int s = 0; s < 4; s++) {
        int idx = tid + s*128;          // 0..511
        int jj = idx >> 3, dd = idx & 7;
        Us[jj][64+dd] = sape[(m0+jj)*ND + dd];
    }
    __syncthreads();

    // gate epilogue: 64(j) x 128(o) = (Us[:,0:72]) @ [Wg;Wsp]
    int tx = tid & 15;      // 4 o's starting tx*4 (left half), +64 (right half)
    int ty = tid >> 4;      // 8 j's starting ty*8
    float accL[8][4] = {}, accR[8][4] = {};
    const float* wg = Wg + l*NC*128;
    #pragma unroll 4
    for (int c = 0; c < NC; c++) {
        float4 wl = *reinterpret_cast<const float4*>(wg + c*128 + tx*4);
        float4 wr = *reinterpret_cast<const float4*>(wg + c*128 + 64 + tx*4);
        #pragma unroll
        for (int jj = 0; jj < 8; jj++) {
            float uv = Us[ty*8+jj][c];
            accL[jj][0] += uv*wl.x; accL[jj][1] += uv*wl.y;
            accL[jj][2] += uv*wl.z; accL[jj][3] += uv*wl.w;
            accR[jj][0] += uv*wr.x; accR[jj][1] += uv*wr.y;
            accR[jj][2] += uv*wr.z; accR[jj][3] += uv*wr.w;
        }
    }
    const float* wsp = Wsp + l*ND*128;
    #pragma unroll
    for (int dd = 0; dd < ND; dd++) {
        float4 wl = *reinterpret_cast<const float4*>(wsp + dd*128 + tx*4);
        float4 wr = *reinterpret_cast<const float4*>(wsp + dd*128 + 64 + tx*4);
        #pragma unroll
        for (int jj = 0; jj < 8; jj++) {
            float uv = Us[ty*8+jj][64+dd];
            accL[jj][0] += uv*wl.x; accL[jj][1] += uv*wl.y;
            accL[jj][2] += uv*wl.z; accL[jj][3] += uv*wl.w;
            accR[jj][0] += uv*wr.x; accR[jj][1] += uv*wr.y;
            accR[jj][2] += uv*wr.z; accR[jj][3] += uv*wr.w;
        }
    }
    float4 tel = *reinterpret_cast<const float4*>(te_s + tx*4);
    float4 ter = *reinterpret_cast<const float4*>(te_s + 64 + tx*4);
    #pragma unroll
    for (int jj = 0; jj < 8; jj++) {
        float4 hv;
        hv.x = (accL[jj][0]+tel.x) * sigm(accR[jj][0]+ter.x);
        hv.y = (accL[jj][1]+tel.y) * sigm(accR[jj][1]+ter.y);
        hv.z = (accL[jj][2]+tel.z) * sigm(accR[jj][2]+ter.z);
        hv.w = (accL[jj][3]+tel.w) * sigm(accR[jj][3]+ter.w);
        *reinterpret_cast<float4*>(hout + (size_t)((b*NT+t)*NV + m0 + ty*8 + jj)*NC + tx*4) = hv;
    }
}

// ---- GFS (time conv) + GLU1 -> skips ----
__global__ void __launch_bounds__(128) k_gfs(const float* __restrict__ fs_b,
                                             const float* __restrict__ g1b, int l) {
    const float* hcur = (l & 1) ? g_hA : g_hB;   // output buffer of layer l
    int b  = blockIdx.x >> 6;
    int v0 = (blockIdx.x & 63) << 3;
    __shared__ float hs[8][NN];
    __shared__ float red[2][NC][8];
    __shared__ float ysh[8][NC];
    __shared__ float zsh[8][2*NC];
    int tid = threadIdx.x;
    for (int idx = tid; idx < 8*NN; idx += 128) {
        int vv = idx / NN; int tc = idx % NN;
        int t = tc >> 6, c = tc & 63;
        hs[vv][tc] = hcur[(size_t)((b*NT+t)*NV + v0+vv)*NC + c];
    }
    __syncthreads();
    int oo = tid & 63, half = tid >> 6;
    const float* fwT = g_fswT + l*NN*NC;
    float part[8] = {};
    for (int c = half*32; c < half*32 + 32; c++) {
        #pragma unroll
        for (int t = 0; t < NT; t++) {
            float w = fwT[(c*NT + t)*NC + oo];
            #pragma unroll
            for (int vv = 0; vv < 8; vv++) part[vv] += hs[vv][t*NC + c]*w;
        }
    }
    #pragma unroll
    for (int vv = 0; vv < 8; vv++) red[half][oo][vv] = part[vv];
    __syncthreads();
    if (half == 0) {
        float fb = fs_b[l*NC + oo];
        #pragma unroll
        for (int vv = 0; vv < 8; vv++) ysh[vv][oo] = red[0][oo][vv] + red[1][oo][vv] + fb;
    }
    __syncthreads();
    const float* gT = g_g1wT + l*NC*2*NC;
    float zacc[8];
    float zb = g1b[l*2*NC + tid];
    #pragma unroll
    for (int vv = 0; vv < 8; vv++) zacc[vv] = zb;
    for (int c = 0; c < NC; c++) {
        float w = gT[c*128 + tid];
        #pragma unroll
        for (int vv = 0; vv < 8; vv++) zacc[vv] += ysh[vv][c]*w;
    }
    #pragma unroll
    for (int vv = 0; vv < 8; vv++) zsh[vv][tid] = zacc[vv];
    __syncthreads();
    if (tid < NC) {
        #pragma unroll
        for (int vv = 0; vv < 8; vv++) {
            float zl = zsh[vv][tid], zr = zsh[vv][tid+NC];
            g_skips[(size_t)(b*NV + v0+vv)*256 + l*NC + tid] = zl * sigm(zr);
        }
    }
}

// ---- output GLU + head ----
__global__ void __launch_bounds__(256) k_out(const float* __restrict__ gout_b,
                                             const float* __restrict__ out_b,
                                             float* __restrict__ out) {
    int b  = blockIdx.x >> 5;
    int v0 = (blockIdx.x & 31) << 4;
    __shared__ float sin_[256][16];
    __shared__ float ssh[256][16];
    int tid = threadIdx.x;
    for (int idx = tid; idx < 256*16; idx += 256) {
        int vv = idx >> 8, ch = idx & 255;
        sin_[ch][vv] = g_skips[(size_t)(b*NV + v0+vv)*256 + ch];
    }
    __syncthreads();
    int o = tid;
    float a0[16] = {}, a1[16] = {};
    for (int c = 0; c < 256; c++) {
        float w0 = g_goutT[c*512 + o];
        float w1 = g_goutT[c*512 + o + 256];
        #pragma unroll
        for (int vv = 0; vv < 16; vv++) {
            float s = sin_[c][vv];
            a0[vv] += w0*s; a1[vv] += w1*s;
        }
    }
    float b0 = gout_b[o], b1 = gout_b[o+256];
    #pragma unroll
    for (int vv = 0; vv < 16; vv++) ssh[o][vv] = (a0[vv]+b0) * sigm(a1[vv]+b1);
    __syncthreads();
    if (tid < NP*16) {
        int p = tid >> 4, vv = tid & 15;
        float a = out_b[p];
        for (int c = 0; c < 256; c++) a += ssh[c][vv]*g_outT[c*NP + p];
        out[(b*NP + p)*NV + v0 + vv] = a;
    }
}

extern "C" void kernel_launch(void* const* d_in, const int* in_sizes, int n_in,
                              void* d_out, int out_size) {
    const float* x      = (const float*)d_in[0];
    const float* sape   = (const float*)d_in[1];
    const float* tape   = (const float*)d_in[2];
    const float* srpe   = (const float*)d_in[3];
    const float* trpe   = (const float*)d_in[4];
    const float* mask   = (const float*)d_in[7];
    const float* Wi     = (const float*)d_in[8];
    const float* bi     = (const float*)d_in[9];
    const float* gc_mu  = (const float*)d_in[10];
    const float* gc_sig = (const float*)d_in[11];
    const float* Wg     = (const float*)d_in[12];
    const float* bg     = (const float*)d_in[13];
    const float* Wsp    = (const float*)d_in[14];
    const float* Wtp    = (const float*)d_in[15];
    const float* fs_w   = (const float*)d_in[16];
    const float* fs_b   = (const float*)d_in[17];
    const float* g1w    = (const float*)d_in[18];
    const float* g1b    = (const float*)d_in[19];
    const float* goutw  = (const float*)d_in[20];
    const float* goutb  = (const float*)d_in[21];
    const float* outw   = (const float*)d_in[22];
    const float* outb   = (const float*)d_in[23];
    float* out = (float*)d_out;

    k_transw<<<1420, 256>>>(fs_w, g1w, goutw, outw);
    k_input<<<6144, 256>>>(x, Wi, bi);
    k_prep<<<NL, 512>>>(sape, tape, trpe, gc_mu, gc_sig);
    k_ebase<<<dim3(1024, NL), 256>>>(srpe, gc_mu, gc_sig);
    for (int l = 0; l < NL; l++) {
        dim3 gg(NT, NV/BM, NB);   // (12, 8, 4) = 384 blocks
        k_gconv<<<gg, 128>>>(mask, sape, tape, Wg, bg, Wsp, Wtp, l);
        k_gfs<<<NB*NV/8, 128>>>(fs_b, g1b, l);
    }
    k_out<<<NB*NV/16, 256>>>(goutb, outb, out);
}

// round 6
// speedup vs baseline: 1.8366x; 1.6212x over previous
#include <cuda_runtime.h>
#include <cuda_bf16.h>
#include <cstdint>
#include <math.h>

// ---- problem constants ----
#define NB 4
#define NT 12
#define NV 512
#define NC 64
#define ND 8
#define NTS 3
#define NP 12
#define NL 4
#define NM (NTS*NV)   // 1536
#define NN (NT*NC)    // 768

// ---- scratch (device globals) ----
__device__ float g_hTA[NB*NT*NC*NV];      // h transposed: [b][t][c][v]
__device__ float g_hTB[NB*NT*NC*NV];
__device__ float g_EbT[NL*NV*NV];         // [l][j][i]
__device__ float g_gs0[NL*NV];
__device__ float g_gs1[NL*NV];
__device__ float g_ept[NL*NB*NT*NTS];
__device__ float g_skips[NB*NV*4*NC];
__device__ float g_fswT[NL*NN*NC];
__device__ float g_g1wT[NL*NC*2*NC];
__device__ float g_goutT[256*512];
__device__ float g_outT[256*NP];
__device__ __nv_bfloat16 g_Ahi[(size_t)NL*NB*NV*NM];   // split A = mask*EbT
__device__ __nv_bfloat16 g_Alo[(size_t)NL*NB*NV*NM];

__device__ __forceinline__ float sigm(float x) { return 1.0f/(1.0f+expf(-x)); }

__device__ __forceinline__ uint32_t smem_u32(const void* p) {
    uint32_t a;
    asm("{ .reg .u64 tmp; cvta.to.shared.u64 tmp, %1; cvt.u32.u64 %0, tmp; }"
        : "=r"(a) : "l"(p));
    return a;
}
__device__ __forceinline__ void ldmx4(uint32_t& r0, uint32_t& r1, uint32_t& r2, uint32_t& r3,
                                      uint32_t addr) {
    asm volatile("ldmatrix.sync.aligned.m8n8.x4.shared.b16 {%0,%1,%2,%3}, [%4];"
        : "=r"(r0), "=r"(r1), "=r"(r2), "=r"(r3) : "r"(addr));
}
__device__ __forceinline__ void mma16816(float* c, const uint32_t* a, const uint32_t* b) {
    asm volatile("mma.sync.aligned.m16n8k16.row.col.f32.bf16.bf16.f32 "
        "{%0,%1,%2,%3}, {%4,%5,%6,%7}, {%8,%9}, {%0,%1,%2,%3};"
        : "+f"(c[0]), "+f"(c[1]), "+f"(c[2]), "+f"(c[3])
        : "r"(a[0]), "r"(a[1]), "r"(a[2]), "r"(a[3]), "r"(b[0]), "r"(b[1]));
}

// ---- one-time weight transposes ----
__global__ void k_transw(const float* __restrict__ fs_w, const float* __restrict__ g1w,
                         const float* __restrict__ gout_w, const float* __restrict__ out_w) {
    int idx = blockIdx.x*256 + threadIdx.x;
    if (idx < NL*NN*NC) {
        int l = idx / (NN*NC); int r = idx % (NN*NC); int ct = r >> 6; int oo = r & 63;
        g_fswT[idx] = fs_w[l*NC*NN + oo*NN + ct];
        return;
    }
    idx -= NL*NN*NC;
    if (idx < NL*NC*2*NC) {
        int l = idx / (NC*2*NC); int r = idx % (NC*2*NC); int c = r >> 7; int o = r & 127;
        g_g1wT[idx] = g1w[l*2*NC*NC + o*NC + c];
        return;
    }
    idx -= NL*NC*2*NC;
    if (idx < 256*512) {
        int c = idx >> 9; int o = idx & 511;
        g_goutT[idx] = gout_w[o*256 + c];
        return;
    }
    idx -= 256*512;
    if (idx < 256*NP) {
        int c = idx / NP; int p = idx % NP;
        g_outT[idx] = out_w[p*256 + c];
    }
}

// ---- input layer (transposed h out) ----
__global__ void k_input(const float* __restrict__ x, const float* __restrict__ Wi,
                        const float* __restrict__ bi) {
    int idx = blockIdx.x*256 + threadIdx.x;
    int v = idx & 511;
    int c = (idx >> 9) & 63;
    int bt = idx >> 15;
    g_hTA[idx] = x[bt*NV + v]*Wi[c] + bi[c];
}

// ---- per-layer small precompute ----
__global__ void k_prep(const float* __restrict__ sape, const float* __restrict__ tape,
                       const float* __restrict__ trpe, const float* __restrict__ gc_mu,
                       const float* __restrict__ gc_sig) {
    int l = blockIdx.x;
    const float* mu = gc_mu + l*6*ND;
    const float* sg = gc_sig + l*6*ND;
    __shared__ float gt2[NB*NT];
    __shared__ float gt3[NB*(NT+2)];
    __shared__ float gt5[NTS];
    int tid = threadIdx.x;  // 512
    if (tid < NV) {
        float a0 = 0.f, a1 = 0.f;
        #pragma unroll
        for (int dd = 0; dd < ND; dd++) {
            float e = sape[tid*ND + dd];
            float d0 = e - mu[0*ND+dd], d1 = e - mu[1*ND+dd];
            a0 += -0.5f*d0*d0*sg[0*ND+dd]*sg[0*ND+dd];
            a1 += -0.5f*d1*d1*sg[1*ND+dd]*sg[1*ND+dd];
        }
        g_gs0[l*NV+tid] = a0; g_gs1[l*NV+tid] = a1;
    }
    if (tid < NB*NT) {
        float a = 0.f;
        #pragma unroll
        for (int dd = 0; dd < ND; dd++) {
            float e = tape[tid*ND + dd]; float dv = e - mu[2*ND+dd];
            a += -0.5f*dv*dv*sg[2*ND+dd]*sg[2*ND+dd];
        }
        gt2[tid] = a;
    }
    if (tid < NB*(NT+2)) {
        int b = tid/(NT+2), tau = tid%(NT+2);
        float a = 0.f;
        #pragma unroll
        for (int dd = 0; dd < ND; dd++) {
            float e = (tau < 2) ? 0.0f : tape[(b*NT + (tau-2))*ND + dd];
            float dv = e - mu[3*ND+dd];
            a += -0.5f*dv*dv*sg[3*ND+dd]*sg[3*ND+dd];
        }
        gt3[tid] = a;
    }
    if (tid < NTS) {
        float a = 0.f;
        #pragma unroll
        for (int dd = 0; dd < ND; dd++) {
            float e = trpe[tid*ND + dd]; float dv = e - mu[5*ND+dd];
            a += -0.5f*dv*dv*sg[5*ND+dd]*sg[5*ND+dd];
        }
        gt5[tid] = a;
    }
    __syncthreads();
    if (tid < NB*NT*NTS) {
        int k = tid % NTS; int bt = tid / NTS;
        int b = bt / NT, t = bt % NT;
        g_ept[l*NB*NT*NTS + tid] = expf(gt2[bt] + gt3[b*(NT+2) + t + k] + gt5[k]);
    }
}

// ---- Ebase^T per layer ----
__global__ void k_ebase(const float* __restrict__ srpe, const float* __restrict__ gc_mu,
                        const float* __restrict__ gc_sig) {
    int l = blockIdx.y;
    int idx = blockIdx.x*256 + threadIdx.x;
    int i = idx >> 9, j = idx & 511;
    const float* mu = gc_mu + l*48 + 32;
    const float* sg = gc_sig + l*48 + 32;
    const float* e = srpe + (size_t)idx*ND;
    float a = 0.f;
    #pragma unroll
    for (int dd = 0; dd < ND; dd++) {
        float dv = e[dd] - mu[dd];
        a += -0.5f*dv*dv*sg[dd]*sg[dd];
    }
    g_EbT[l*NV*NV + j*NV + i] = expf(a + g_gs0[l*NV+i] + g_gs1[l*NV+j]);
}

// ---- split A = mask*EbT into bf16 hi/lo ----
__global__ void k_asplit(const float* __restrict__ mask) {
    size_t gidx = (size_t)blockIdx.x*256 + threadIdx.x;
    size_t g = gidx;
    int mq = (int)(g % 384); g /= 384;
    int j  = (int)(g % 512); g /= 512;
    int b  = (int)(g % 4);
    int l  = (int)(g / 4);
    int m = mq*4, i = m & 511;
    float4 mv = *(const float4*)(mask + (((size_t)b*NV + j)*NM + m));
    float4 ev = *(const float4*)(g_EbT + ((size_t)l*NV + j)*NV + i);
    float a[4] = {mv.x*ev.x, mv.y*ev.y, mv.z*ev.z, mv.w*ev.w};
    union { __nv_bfloat16 h[4]; uint2 u; } Hi, Lo;
    #pragma unroll
    for (int q = 0; q < 4; q++) {
        __nv_bfloat16 hh = __float2bfloat16(a[q]);
        Hi.h[q] = hh;
        Lo.h[q] = __float2bfloat16(a[q] - __bfloat162float(hh));
    }
    size_t off = (((size_t)l*NB + b)*NV + j)*NM + m;
    *(uint2*)(g_Ahi + off) = Hi.u;
    *(uint2*)(g_Alo + off) = Lo.u;
}

// ================= warp-MMA fused graph-conv + gate =================
// smem layout (bytes):
#define OFF_TE   0        // 512
#define OFF_US   512      // 128*73*4 = 37376 -> 37888
#define OFF_AHI  37888    // 128*40*2 = 10240 -> 48128
#define OFF_ALO  48128    // 10240 -> 58368
#define OFF_BHI  58368    // 64*40*2 = 5120 -> 63488
#define OFF_BLO  63488    // 5120 -> 68608
#define OFF_HS   37888    // 64*132*4 = 33792 -> 71680 (reuses dead A/B region)
#define SMEM_TOTAL 71680
#define USP 73
#define HSP 132
#define APITCH 40         // bf16 elems per row (pad for ldmatrix bank spread)

__global__ void __launch_bounds__(128) k_gconv_mma(const float* __restrict__ sape,
                                                   const float* __restrict__ tape,
                                                   const float* __restrict__ Wg,
                                                   const float* __restrict__ bg,
                                                   const float* __restrict__ Wsp,
                                                   const float* __restrict__ Wtp, int l) {
    extern __shared__ __align__(1024) char smem[];
    const float* hin  = (l & 1) ? g_hTB : g_hTA;
    float*       hout = (l & 1) ? g_hTA : g_hTB;
    int b  = blockIdx.z;
    int t  = blockIdx.x;
    int m0 = blockIdx.y * 128;
    int tid = threadIdx.x, wid = tid >> 5, lane = tid & 31;
    uint32_t sb = smem_u32(smem);

    // te = bg + tape@Wtp
    {
        float a = bg[l*128 + tid];
        #pragma unroll
        for (int dd = 0; dd < ND; dd++)
            a += tape[(b*NT+t)*ND + dd] * Wtp[(l*ND + dd)*128 + tid];
        ((float*)(smem + OFF_TE))[tid] = a;
    }

    float eptv[NTS];
    const float* hb3[NTS];
    #pragma unroll
    for (int k = 0; k < NTS; k++) {
        int tt = t + k - 2;
        eptv[k] = (tt >= 0) ? g_ept[l*NB*NT*NTS + (b*NT + t)*NTS + k] : 0.0f;
        hb3[k]  = (tt >= 0) ? (hin + (size_t)(b*NT + tt)*NC*NV) : hin;
    }
    const __nv_bfloat16* Ahig = g_Ahi + (((size_t)l*NB + b)*NV + m0)*NM;
    const __nv_bfloat16* Alog = g_Alo + (((size_t)l*NB + b)*NV + m0)*NM;

    float acc[2][8][4];
    #pragma unroll
    for (int mt = 0; mt < 2; mt++)
        #pragma unroll
        for (int nb = 0; nb < 8; nb++)
            #pragma unroll
            for (int q = 0; q < 4; q++) acc[mt][nb][q] = 0.f;

    // ldmatrix address precompute (lane-dependent parts)
    int lj = lane >> 3, li = lane & 7;

    for (int ch = 0; ch < 48; ch++) {       // 48 chunks of K=32
        int kw = ch >> 4;
        int i0 = (ch & 15) * 32;
        // --- load A hi/lo [128][32] ---
        #pragma unroll
        for (int s = 0; s < 4; s++) {
            int task = tid + s*128;         // 0..511
            int row = task >> 2, q = task & 3;
            size_t goff = (size_t)row*NM + ch*32 + q*8;
            uint4 vh = *(const uint4*)(Ahig + goff);
            uint4 vl = *(const uint4*)(Alog + goff);
            uint32_t soff = (uint32_t)(row*APITCH + q*8)*2;
            *(uint4*)(smem + OFF_AHI + soff) = vh;
            *(uint4*)(smem + OFF_ALO + soff) = vl;
        }
        // --- gen B hi/lo [64 n(c)][32 k] from ept*hT ---
        {
            float ep = eptv[kw];
            const float* hb = hb3[kw];
            #pragma unroll
            for (int s = 0; s < 2; s++) {
                int task = tid + s*128;     // 0..255
                int c = task >> 2, q = task & 3;
                const float* hp = hb + (size_t)c*NV + i0 + q*8;
                float4 h0 = *(const float4*)hp;
                float4 h1 = *(const float4*)(hp + 4);
                float v[8] = {h0.x,h0.y,h0.z,h0.w,h1.x,h1.y,h1.z,h1.w};
                union { __nv_bfloat16 bh[8]; uint4 u; } Hi, Lo;
                #pragma unroll
                for (int q2 = 0; q2 < 8; q2++) {
                    float val = ep * v[q2];
                    __nv_bfloat16 hh = __float2bfloat16(val);
                    Hi.bh[q2] = hh;
                    Lo.bh[q2] = __float2bfloat16(val - __bfloat162float(hh));
                }
                uint32_t soff = (uint32_t)(c*APITCH + q*8)*2;
                *(uint4*)(smem + OFF_BHI + soff) = Hi.u;
                *(uint4*)(smem + OFF_BLO + soff) = Lo.u;
            }
        }
        __syncthreads();
        // --- MMA over 2 k16 steps ---
        #pragma unroll
        for (int ks = 0; ks < 32; ks += 16) {
            // B frags: 8 n-blocks, regs [nb][2], hi and lo
            uint32_t bh[8][2], bl[8][2];
            #pragma unroll
            for (int nbp = 0; nbp < 4; nbp++) {
                int nrow = (nbp*2 + (lj>>1))*8 + li;
                int col  = ks + ((lj&1)<<3);
                uint32_t addr = (uint32_t)(nrow*APITCH + col)*2;
                ldmx4(bh[nbp*2][0], bh[nbp*2][1], bh[nbp*2+1][0], bh[nbp*2+1][1],
                      sb + OFF_BHI + addr);
                ldmx4(bl[nbp*2][0], bl[nbp*2][1], bl[nbp*2+1][0], bl[nbp*2+1][1],
                      sb + OFF_BLO + addr);
            }
            #pragma unroll
            for (int mt = 0; mt < 2; mt++) {
                int arow = wid*32 + mt*16 + ((lj&1)<<3) + li;
                int acol = ks + ((lj>>1)<<3);
                uint32_t addr = (uint32_t)(arow*APITCH + acol)*2;
                uint32_t ah[4], al[4];
                ldmx4(ah[0], ah[1], ah[2], ah[3], sb + OFF_AHI + addr);
                ldmx4(al[0], al[1], al[2], al[3], sb + OFF_ALO + addr);
                #pragma unroll
                for (int nb = 0; nb < 8; nb++) {
                    mma16816(acc[mt][nb], ah, bh[nb]);
                    mma16816(acc[mt][nb], ah, bl[nb]);
                    mma16816(acc[mt][nb], al, bh[nb]);
                }
            }
        }
        __syncthreads();
    }

    // ---- stage u tile (+ sape ext cols) in Us ----
    {
        float* Us = (float*)(smem + OFF_US);
        int r0 = wid*32 + (lane>>2);
        int c0 = (lane&3)*2;
        #pragma unroll
        for (int mt = 0; mt < 2; mt++) {
            #pragma unroll
            for (int nb = 0; nb < 8; nb++) {
                int rr = r0 + mt*16;
                int cc = nb*8 + c0;
                Us[rr*USP + cc]     = acc[mt][nb][0];
                Us[rr*USP + cc+1]   = acc[mt][nb][1];
                Us[(rr+8)*USP + cc]   = acc[mt][nb][2];
                Us[(rr+8)*USP + cc+1] = acc[mt][nb][3];
            }
        }
        #pragma unroll
        for (int s = 0; s < 8; s++) {
            int idx = tid + s*128;      // 0..1023
            int jj = idx >> 3, dd = idx & 7;
            Us[jj*USP + 64 + dd] = sape[(m0+jj)*ND + dd];
        }
    }
    __syncthreads();

    // ---- gate: g = u@Wg + sape@Wsp + te; h = gl*sigm(gr) ----
    {
        float* Us = (float*)(smem + OFF_US);
        float* Hs = (float*)(smem + OFF_HS);
        const float* te = (const float*)(smem + OFF_TE);
        int tx = tid & 15;
        int ty = tid >> 4;
        float accL[16][4] = {}, accR[16][4] = {};
        const float* wg = Wg + l*NC*128;
        #pragma unroll 4
        for (int c = 0; c < NC; c++) {
            float4 wl = *(const float4*)(wg + c*128 + tx*4);
            float4 wr = *(const float4*)(wg + c*128 + 64 + tx*4);
            #pragma unroll
            for (int jj = 0; jj < 16; jj++) {
                float uv = Us[(ty*16+jj)*USP + c];
                accL[jj][0] += uv*wl.x; accL[jj][1] += uv*wl.y;
                accL[jj][2] += uv*wl.z; accL[jj][3] += uv*wl.w;
                accR[jj][0] += uv*wr.x; accR[jj][1] += uv*wr.y;
                accR[jj][2] += uv*wr.z; accR[jj][3] += uv*wr.w;
            }
        }
        const float* wsp = Wsp + l*ND*128;
        #pragma unroll
        for (int dd = 0; dd < ND; dd++) {
            float4 wl = *(const float4*)(wsp + dd*128 + tx*4);
            float4 wr = *(const float4*)(wsp + dd*128 + 64 + tx*4);
            #pragma unroll
            for (int jj = 0; jj < 16; jj++) {
                float uv = Us[(ty*16+jj)*USP + 64 + dd];
                accL[jj][0] += uv*wl.x; accL[jj][1] += uv*wl.y;
                accL[jj][2] += uv*wl.z; accL[jj][3] += uv*wl.w;
                accR[jj][0] += uv*wr.x; accR[jj][1] += uv*wr.y;
                accR[jj][2] += uv*wr.z; accR[jj][3] += uv*wr.w;
            }
        }
        float tel[4] = {te[tx*4], te[tx*4+1], te[tx*4+2], te[tx*4+3]};
        float ter[4] = {te[64+tx*4], te[64+tx*4+1], te[64+tx*4+2], te[64+tx*4+3]};
        #pragma unroll
        for (int jj = 0; jj < 16; jj++) {
            int j = ty*16 + jj;
            #pragma unroll
            for (int q = 0; q < 4; q++) {
                float hv = (accL[jj][q] + tel[q]) * sigm(accR[jj][q] + ter[q]);
                Hs[(tx*4+q)*HSP + j] = hv;
            }
        }
    }
    __syncthreads();
    // ---- coalesced transposed writeback ----
    {
        const float* Hs = (const float*)(smem + OFF_HS);
        #pragma unroll
        for (int s = 0; s < 16; s++) {
            int idx = tid + s*128;
            int r = idx >> 5, q4 = idx & 31;
            float4 v = *(const float4*)(Hs + r*HSP + q4*4);
            *(float4*)(hout + ((size_t)((b*NT+t)*NC + r))*NV + m0 + q4*4) = v;
        }
    }
}

// ---- GFS (time conv) + GLU1 -> skips ----
__global__ void __launch_bounds__(128) k_gfs(const float* __restrict__ fs_b,
                                             const float* __restrict__ g1b, int l) {
    const float* hcur = (l & 1) ? g_hTA : g_hTB;
    int b  = blockIdx.x >> 6;
    int v0 = (blockIdx.x & 63) << 3;
    __shared__ float hs[8][NN+4];
    __shared__ float red[2][NC][8];
    __shared__ float ysh[8][NC];
    __shared__ float zsh[8][2*NC];
    int tid = threadIdx.x;
    for (int idx = tid; idx < 8*NN; idx += 128) {
        int vv = idx & 7;
        int c  = (idx >> 3) & 63;
        int t  = idx >> 9;
        hs[vv][t*NC + c] = hcur[((size_t)((b*NT+t)*NC + c))*NV + v0 + vv];
    }
    __syncthreads();
    int oo = tid & 63, half = tid >> 6;
    const float* fwT = g_fswT + l*NN*NC;
    float part[8] = {};
    for (int c = half*32; c < half*32 + 32; c++) {
        #pragma unroll
        for (int t = 0; t < NT; t++) {
            float w = fwT[(c*NT + t)*NC + oo];
            #pragma unroll
            for (int vv = 0; vv < 8; vv++) part[vv] += hs[vv][t*NC + c]*w;
        }
    }
    #pragma unroll
    for (int vv = 0; vv < 8; vv++) red[half][oo][vv] = part[vv];
    __syncthreads();
    if (half == 0) {
        float fb = fs_b[l*NC + oo];
        #pragma unroll
        for (int vv = 0; vv < 8; vv++) ysh[vv][oo] = red[0][oo][vv] + red[1][oo][vv] + fb;
    }
    __syncthreads();
    const float* gT = g_g1wT + l*NC*2*NC;
    float zacc[8];
    float zb = g1b[l*2*NC + tid];
    #pragma unroll
    for (int vv = 0; vv < 8; vv++) zacc[vv] = zb;
    for (int c = 0; c < NC; c++) {
        float w = gT[c*128 + tid];
        #pragma unroll
        for (int vv = 0; vv < 8; vv++) zacc[vv] += ysh[vv][c]*w;
    }
    #pragma unroll
    for (int vv = 0; vv < 8; vv++) zsh[vv][tid] = zacc[vv];
    __syncthreads();
    if (tid < NC) {
        #pragma unroll
        for (int vv = 0; vv < 8; vv++) {
            float zl = zsh[vv][tid], zr = zsh[vv][tid+NC];
            g_skips[(size_t)(b*NV + v0+vv)*256 + l*NC + tid] = zl * sigm(zr);
        }
    }
}

// ---- output GLU + head ----
__global__ void __launch_bounds__(256) k_out(const float* __restrict__ gout_b,
                                             const float* __restrict__ out_b,
                                             float* __restrict__ out) {
    int b  = blockIdx.x >> 5;
    int v0 = (blockIdx.x & 31) << 4;
    __shared__ float sin_[256][16];
    __shared__ float ssh[256][16];
    int tid = threadIdx.x;
    for (int idx = tid; idx < 256*16; idx += 256) {
        int vv = idx >> 8, ch = idx & 255;
        sin_[ch][vv] = g_skips[(size_t)(b*NV + v0+vv)*256 + ch];
    }
    __syncthreads();
    int o = tid;
    float a0[16] = {}, a1[16] = {};
    for (int c = 0; c < 256; c++) {
        float w0 = g_goutT[c*512 + o];
        float w1 = g_goutT[c*512 + o + 256];
        #pragma unroll
        for (int vv = 0; vv < 16; vv++) {
            float s = sin_[c][vv];
            a0[vv] += w0*s; a1[vv] += w1*s;
        }
    }
    float b0 = gout_b[o], b1 = gout_b[o+256];
    #pragma unroll
    for (int vv = 0; vv < 16; vv++) ssh[o][vv] = (a0[vv]+b0) * sigm(a1[vv]+b1);
    __syncthreads();
    if (tid < NP*16) {
        int p = tid >> 4, vv = tid & 15;
        float a = out_b[p];
        for (int c = 0; c < 256; c++) a += ssh[c][vv]*g_outT[c*NP + p];
        out[(b*NP + p)*NV + v0 + vv] = a;
    }
}

extern "C" void kernel_launch(void* const* d_in, const int* in_sizes, int n_in,
                              void* d_out, int out_size) {
    const float* x      = (const float*)d_in[0];
    const float* sape   = (const float*)d_in[1];
    const float* tape   = (const float*)d_in[2];
    const float* srpe   = (const float*)d_in[3];
    const float* trpe   = (const float*)d_in[4];
    const float* mask   = (const float*)d_in[7];
    const float* Wi     = (const float*)d_in[8];
    const float* bi     = (const float*)d_in[9];
    const float* gc_mu  = (const float*)d_in[10];
    const float* gc_sig = (const float*)d_in[11];
    const float* Wg     = (const float*)d_in[12];
    const float* bg     = (const float*)d_in[13];
    const float* Wsp    = (const float*)d_in[14];
    const float* Wtp    = (const float*)d_in[15];
    const float* fs_w   = (const float*)d_in[16];
    const float* fs_b   = (const float*)d_in[17];
    const float* g1w    = (const float*)d_in[18];
    const float* g1b    = (const float*)d_in[19];
    const float* goutw  = (const float*)d_in[20];
    const float* goutb  = (const float*)d_in[21];
    const float* outw   = (const float*)d_in[22];
    const float* outb   = (const float*)d_in[23];
    float* out = (float*)d_out;

    cudaFuncSetAttribute(k_gconv_mma, cudaFuncAttributeMaxDynamicSharedMemorySize, SMEM_TOTAL);

    k_transw<<<1420, 256>>>(fs_w, g1w, goutw, outw);
    k_input<<<6144, 256>>>(x, Wi, bi);
    k_prep<<<NL, 512>>>(sape, tape, trpe, gc_mu, gc_sig);
    k_ebase<<<dim3(1024, NL), 256>>>(srpe, gc_mu, gc_sig);
    k_asplit<<<12288, 256>>>(mask);
    for (int l = 0; l < NL; l++) {
        dim3 gg(NT, NV/128, NB);   // (12, 4, 4) = 192 CTAs
        k_gconv_mma<<<gg, 128, SMEM_TOTAL>>>(sape, tape, Wg, bg, Wsp, Wtp, l);
        k_gfs<<<NB*NV/8, 128>>>(fs_b, g1b, l);
    }
    k_out<<<NB*NV/16, 256>>>(goutb, outb, out);
}

// round 7
// speedup vs baseline: 1.9901x; 1.0836x over previous
#include <cuda_runtime.h>
#include <cuda_bf16.h>
#include <cstdint>
#include <math.h>

// ---- problem constants ----
#define NB 4
#define NT 12
#define NV 512
#define NC 64
#define ND 8
#define NTS 3
#define NP 12
#define NL 4
#define NM (NTS*NV)   // 1536
#define NN (NT*NC)    // 768

// ---- scratch (device globals) ----
__device__ float g_hTA[NB*NT*NC*NV];      // h transposed: [b][t][c][v]
__device__ float g_hTB[NB*NT*NC*NV];
__device__ float g_EbT[NL*NV*NV];         // [l][j][i]
__device__ float g_gs0[NL*NV];
__device__ float g_gs1[NL*NV];
__device__ float g_ept[NL*NB*NT*NTS];
__device__ float g_skips[NB*NV*4*NC];
__device__ float g_fswT[NL*NN*NC];
__device__ float g_g1wT[NL*NC*2*NC];
__device__ float g_goutT[256*512];
__device__ float g_outT[256*NP];
__device__ __nv_bfloat16 g_Ahi[(size_t)NL*NB*NV*NM];   // split A = mask*EbT
__device__ __nv_bfloat16 g_Alo[(size_t)NL*NB*NV*NM];

__device__ __forceinline__ float sigm(float x) { return 1.0f/(1.0f+expf(-x)); }

__device__ __forceinline__ uint32_t smem_u32(const void* p) {
    uint32_t a;
    asm("{ .reg .u64 tmp; cvta.to.shared.u64 tmp, %1; cvt.u32.u64 %0, tmp; }"
        : "=r"(a) : "l"(p));
    return a;
}
__device__ __forceinline__ void ldmx4(uint32_t& r0, uint32_t& r1, uint32_t& r2, uint32_t& r3,
                                      uint32_t addr) {
    asm volatile("ldmatrix.sync.aligned.m8n8.x4.shared.b16 {%0,%1,%2,%3}, [%4];"
        : "=r"(r0), "=r"(r1), "=r"(r2), "=r"(r3) : "r"(addr));
}
__device__ __forceinline__ void mma16816(float* c, const uint32_t* a, const uint32_t* b) {
    asm volatile("mma.sync.aligned.m16n8k16.row.col.f32.bf16.bf16.f32 "
        "{%0,%1,%2,%3}, {%4,%5,%6,%7}, {%8,%9}, {%0,%1,%2,%3};"
        : "+f"(c[0]), "+f"(c[1]), "+f"(c[2]), "+f"(c[3])
        : "r"(a[0]), "r"(a[1]), "r"(a[2]), "r"(a[3]), "r"(b[0]), "r"(b[1]));
}
#define CP_ASYNC16(saddr, gptr) \
    asm volatile("cp.async.cg.shared.global [%0], [%1], 16;" :: "r"(saddr), "l"(gptr))
#define CP_COMMIT() asm volatile("cp.async.commit_group;" ::: "memory")
#define CP_WAIT1()  asm volatile("cp.async.wait_group 1;" ::: "memory")
#define CP_WAIT0()  asm volatile("cp.async.wait_group 0;" ::: "memory")

// ---- one-time weight transposes ----
__global__ void k_transw(const float* __restrict__ fs_w, const float* __restrict__ g1w,
                         const float* __restrict__ gout_w, const float* __restrict__ out_w) {
    int idx = blockIdx.x*256 + threadIdx.x;
    if (idx < NL*NN*NC) {
        int l = idx / (NN*NC); int r = idx % (NN*NC); int ct = r >> 6; int oo = r & 63;
        g_fswT[idx] = fs_w[l*NC*NN + oo*NN + ct];
        return;
    }
    idx -= NL*NN*NC;
    if (idx < NL*NC*2*NC) {
        int l = idx / (NC*2*NC); int r = idx % (NC*2*NC); int c = r >> 7; int o = r & 127;
        g_g1wT[idx] = g1w[l*2*NC*NC + o*NC + c];
        return;
    }
    idx -= NL*NC*2*NC;
    if (idx < 256*512) {
        int c = idx >> 9; int o = idx & 511;
        g_goutT[idx] = gout_w[o*256 + c];
        return;
    }
    idx -= 256*512;
    if (idx < 256*NP) {
        int c = idx / NP; int p = idx % NP;
        g_outT[idx] = out_w[p*256 + c];
    }
}

// ---- input layer (transposed h out) ----
__global__ void k_input(const float* __restrict__ x, const float* __restrict__ Wi,
                        const float* __restrict__ bi) {
    int idx = blockIdx.x*256 + threadIdx.x;
    int v = idx & 511;
    int c = (idx >> 9) & 63;
    int bt = idx >> 15;
    g_hTA[idx] = x[bt*NV + v]*Wi[c] + bi[c];
}

// ---- per-layer small precompute ----
__global__ void k_prep(const float* __restrict__ sape, const float* __restrict__ tape,
                       const float* __restrict__ trpe, const float* __restrict__ gc_mu,
                       const float* __restrict__ gc_sig) {
    int l = blockIdx.x;
    const float* mu = gc_mu + l*6*ND;
    const float* sg = gc_sig + l*6*ND;
    __shared__ float gt2[NB*NT];
    __shared__ float gt3[NB*(NT+2)];
    __shared__ float gt5[NTS];
    int tid = threadIdx.x;  // 512
    if (tid < NV) {
        float a0 = 0.f, a1 = 0.f;
        #pragma unroll
        for (int dd = 0; dd < ND; dd++) {
            float e = sape[tid*ND + dd];
            float d0 = e - mu[0*ND+dd], d1 = e - mu[1*ND+dd];
            a0 += -0.5f*d0*d0*sg[0*ND+dd]*sg[0*ND+dd];
            a1 += -0.5f*d1*d1*sg[1*ND+dd]*sg[1*ND+dd];
        }
        g_gs0[l*NV+tid] = a0; g_gs1[l*NV+tid] = a1;
    }
    if (tid < NB*NT) {
        float a = 0.f;
        #pragma unroll
        for (int dd = 0; dd < ND; dd++) {
            float e = tape[tid*ND + dd]; float dv = e - mu[2*ND+dd];
            a += -0.5f*dv*dv*sg[2*ND+dd]*sg[2*ND+dd];
        }
        gt2[tid] = a;
    }
    if (tid < NB*(NT+2)) {
        int b = tid/(NT+2), tau = tid%(NT+2);
        float a = 0.f;
        #pragma unroll
        for (int dd = 0; dd < ND; dd++) {
            float e = (tau < 2) ? 0.0f : tape[(b*NT + (tau-2))*ND + dd];
            float dv = e - mu[3*ND+dd];
            a += -0.5f*dv*dv*sg[3*ND+dd]*sg[3*ND+dd];
        }
        gt3[tid] = a;
    }
    if (tid < NTS) {
        float a = 0.f;
        #pragma unroll
        for (int dd = 0; dd < ND; dd++) {
            float e = trpe[tid*ND + dd]; float dv = e - mu[5*ND+dd];
            a += -0.5f*dv*dv*sg[5*ND+dd]*sg[5*ND+dd];
        }
        gt5[tid] = a;
    }
    __syncthreads();
    if (tid < NB*NT*NTS) {
        int k = tid % NTS; int bt = tid / NTS;
        int b = bt / NT, t = bt % NT;
        g_ept[l*NB*NT*NTS + tid] = expf(gt2[bt] + gt3[b*(NT+2) + t + k] + gt5[k]);
    }
}

// ---- Ebase^T per layer ----
__global__ void k_ebase(const float* __restrict__ srpe, const float* __restrict__ gc_mu,
                        const float* __restrict__ gc_sig) {
    int l = blockIdx.y;
    int idx = blockIdx.x*256 + threadIdx.x;
    int i = idx >> 9, j = idx & 511;
    const float* mu = gc_mu + l*48 + 32;
    const float* sg = gc_sig + l*48 + 32;
    const float* e = srpe + (size_t)idx*ND;
    float a = 0.f;
    #pragma unroll
    for (int dd = 0; dd < ND; dd++) {
        float dv = e[dd] - mu[dd];
        a += -0.5f*dv*dv*sg[dd]*sg[dd];
    }
    g_EbT[l*NV*NV + j*NV + i] = expf(a + g_gs0[l*NV+i] + g_gs1[l*NV+j]);
}

// ---- split A = mask*EbT into bf16 hi/lo ----
__global__ void k_asplit(const float* __restrict__ mask) {
    size_t gidx = (size_t)blockIdx.x*256 + threadIdx.x;
    size_t g = gidx;
    int mq = (int)(g % 384); g /= 384;
    int j  = (int)(g % 512); g /= 512;
    int b  = (int)(g % 4);
    int l  = (int)(g / 4);
    int m = mq*4, i = m & 511;
    float4 mv = *(const float4*)(mask + (((size_t)b*NV + j)*NM + m));
    float4 ev = *(const float4*)(g_EbT + ((size_t)l*NV + j)*NV + i);
    float a[4] = {mv.x*ev.x, mv.y*ev.y, mv.z*ev.z, mv.w*ev.w};
    union { __nv_bfloat16 h[4]; uint2 u; } Hi, Lo;
    #pragma unroll
    for (int q = 0; q < 4; q++) {
        __nv_bfloat16 hh = __float2bfloat16(a[q]);
        Hi.h[q] = hh;
        Lo.h[q] = __float2bfloat16(a[q] - __bfloat162float(hh));
    }
    size_t off = (((size_t)l*NB + b)*NV + j)*NM + m;
    *(uint2*)(g_Ahi + off) = Hi.u;
    *(uint2*)(g_Alo + off) = Lo.u;
}

// ================= pipelined warp-MMA fused graph-conv + gate =================
// smem layout (bytes):
#define OFF_TE    0        // 512
#define OFF_AHI   512      // 2 stages x 10240 -> 512..20992
#define OFF_ALO   20992    // 2 stages x 10240 -> ..41472
#define OFF_BHI   41472    // 2 stages x 5120  -> ..51712
#define OFF_BLO   51712    // 2 stages x 5120  -> ..61952
#define OFF_US    512      // 128*73*4 = 37376 -> ..37888 (after mainloop; overlaps A)
#define OFF_HS    37888    // 64*132*4 = 33792 -> ..71680 (overlaps A/B tail)
#define SMEM_TOTAL 71680
#define USP 73
#define HSP 132
#define APITCH 40          // bf16 elems per row (pad for ldmatrix bank spread)
#define A_ST 10240
#define B_ST 5120

__global__ void __launch_bounds__(128) k_gconv_mma(const float* __restrict__ sape,
                                                   const float* __restrict__ tape,
                                                   const float* __restrict__ Wg,
                                                   const float* __restrict__ bg,
                                                   const float* __restrict__ Wsp,
                                                   const float* __restrict__ Wtp, int l) {
    extern __shared__ __align__(1024) char smem[];
    const float* hin  = (l & 1) ? g_hTB : g_hTA;
    float*       hout = (l & 1) ? g_hTA : g_hTB;
    int b  = blockIdx.z;
    int t  = blockIdx.x;
    int m0 = blockIdx.y * 128;
    int tid = threadIdx.x, wid = tid >> 5, lane = tid & 31;
    uint32_t sb = smem_u32(smem);

    // te = bg + tape@Wtp
    {
        float a = bg[l*128 + tid];
        #pragma unroll
        for (int dd = 0; dd < ND; dd++)
            a += tape[(b*NT+t)*ND + dd] * Wtp[(l*ND + dd)*128 + tid];
        ((float*)(smem + OFF_TE))[tid] = a;
    }

    float eptv[NTS];
    const float* hb3[NTS];
    #pragma unroll
    for (int k = 0; k < NTS; k++) {
        int tt = t + k - 2;
        eptv[k] = (tt >= 0) ? g_ept[l*NB*NT*NTS + (b*NT + t)*NTS + k] : 0.0f;
        hb3[k]  = (tt >= 0) ? (hin + (size_t)(b*NT + tt)*NC*NV) : hin;
    }
    const __nv_bfloat16* Ahig = g_Ahi + (((size_t)l*NB + b)*NV + m0)*NM;
    const __nv_bfloat16* Alog = g_Alo + (((size_t)l*NB + b)*NV + m0)*NM;

    // per-thread copy/gen task coords (constant across chunks)
    const int arow = tid >> 2, aq = tid & 3;          // with s-stride 128: rows via task>>2
    const int bc = tid >> 2, bq = tid & 3;            // B tasks (2 per thread)

    float acc[2][8][4];
    #pragma unroll
    for (int mt = 0; mt < 2; mt++)
        #pragma unroll
        for (int nb = 0; nb < 8; nb++)
            #pragma unroll
            for (int q = 0; q < 4; q++) acc[mt][nb][q] = 0.f;

    float hreg[16];

    // ---- prologue: issue A(0) cp.async, load h(0) into regs ----
    {
        #pragma unroll
        for (int s = 0; s < 4; s++) {
            int task = tid + s*128;
            int row = task >> 2, q = task & 3;
            size_t goff = (size_t)row*NM + q*8;
            uint32_t soff = (uint32_t)(row*APITCH + q*8)*2;
            CP_ASYNC16(sb + OFF_AHI + soff, Ahig + goff);
            CP_ASYNC16(sb + OFF_ALO + soff, Alog + goff);
        }
        CP_COMMIT();
        float ep = eptv[0];
        const float* hb = hb3[0];
        #pragma unroll
        for (int s = 0; s < 2; s++) {
            int task = tid + s*128;
            int c = task >> 2, q = task & 3;
            const float* hp = hb + (size_t)c*NV + q*8;
            float4 h0 = *(const float4*)hp;
            float4 h1 = *(const float4*)(hp + 4);
            hreg[s*8+0]=ep*h0.x; hreg[s*8+1]=ep*h0.y; hreg[s*8+2]=ep*h0.z; hreg[s*8+3]=ep*h0.w;
            hreg[s*8+4]=ep*h1.x; hreg[s*8+5]=ep*h1.y; hreg[s*8+6]=ep*h1.z; hreg[s*8+7]=ep*h1.w;
        }
    }

    int lj = lane >> 3, li = lane & 7;

    for (int ch = 0; ch < 48; ch++) {
        int st = ch & 1, nst = st ^ 1;
        // (1) issue A(ch+1) into other stage
        if (ch < 47) {
            int nch = ch + 1;
            #pragma unroll
            for (int s = 0; s < 4; s++) {
                int task = tid + s*128;
                int row = task >> 2, q = task & 3;
                size_t goff = (size_t)row*NM + nch*32 + q*8;
                uint32_t soff = (uint32_t)(row*APITCH + q*8)*2;
                CP_ASYNC16(sb + OFF_AHI + nst*A_ST + soff, Ahig + goff);
                CP_ASYNC16(sb + OFF_ALO + nst*A_ST + soff, Alog + goff);
            }
            CP_COMMIT();
        }
        // (2) convert B(ch) from hreg -> Bs[st]
        {
            #pragma unroll
            for (int s = 0; s < 2; s++) {
                int task = tid + s*128;
                int c = task >> 2, q = task & 3;
                union { __nv_bfloat16 bh[8]; uint4 u; } Hi, Lo;
                #pragma unroll
                for (int q2 = 0; q2 < 8; q2++) {
                    float val = hreg[s*8+q2];
                    __nv_bfloat16 hh = __float2bfloat16(val);
                    Hi.bh[q2] = hh;
                    Lo.bh[q2] = __float2bfloat16(val - __bfloat162float(hh));
                }
                uint32_t soff = (uint32_t)(c*APITCH + q*8)*2;
                *(uint4*)(smem + OFF_BHI + st*B_ST + soff) = Hi.u;
                *(uint4*)(smem + OFF_BLO + st*B_ST + soff) = Lo.u;
            }
        }
        // (3) prefetch h(ch+1) into regs
        if (ch < 47) {
            int nch = ch + 1;
            int kw = nch >> 4;
            int i0 = (nch & 15) * 32;
            float ep = eptv[kw];
            const float* hb = hb3[kw];
            #pragma unroll
            for (int s = 0; s < 2; s++) {
                int task = tid + s*128;
                int c = task >> 2, q = task & 3;
                const float* hp = hb + (size_t)c*NV + i0 + q*8;
                float4 h0 = *(const float4*)hp;
                float4 h1 = *(const float4*)(hp + 4);
                hreg[s*8+0]=ep*h0.x; hreg[s*8+1]=ep*h0.y; hreg[s*8+2]=ep*h0.z; hreg[s*8+3]=ep*h0.w;
                hreg[s*8+4]=ep*h1.x; hreg[s*8+5]=ep*h1.y; hreg[s*8+6]=ep*h1.z; hreg[s*8+7]=ep*h1.w;
            }
        }
        // (4) wait for A(ch)
        if (ch < 47) CP_WAIT1(); else CP_WAIT0();
        __syncthreads();
        // (6) MMA on stage st
        uint32_t baseAH = sb + OFF_AHI + st*A_ST;
        uint32_t baseAL = sb + OFF_ALO + st*A_ST;
        uint32_t baseBH = sb + OFF_BHI + st*B_ST;
        uint32_t baseBL = sb + OFF_BLO + st*B_ST;
        #pragma unroll
        for (int ks = 0; ks < 32; ks += 16) {
            uint32_t bh[8][2], bl[8][2];
            #pragma unroll
            for (int nbp = 0; nbp < 4; nbp++) {
                int nrow = (nbp*2 + (lj>>1))*8 + li;
                int col  = ks + ((lj&1)<<3);
                uint32_t addr = (uint32_t)(nrow*APITCH + col)*2;
                ldmx4(bh[nbp*2][0], bh[nbp*2][1], bh[nbp*2+1][0], bh[nbp*2+1][1], baseBH + addr);
                ldmx4(bl[nbp*2][0], bl[nbp*2][1], bl[nbp*2+1][0], bl[nbp*2+1][1], baseBL + addr);
            }
            #pragma unroll
            for (int mt = 0; mt < 2; mt++) {
                int ar = wid*32 + mt*16 + ((lj&1)<<3) + li;
                int ac = ks + ((lj>>1)<<3);
                uint32_t addr = (uint32_t)(ar*APITCH + ac)*2;
                uint32_t ah[4], al[4];
                ldmx4(ah[0], ah[1], ah[2], ah[3], baseAH + addr);
                ldmx4(al[0], al[1], al[2], al[3], baseAL + addr);
                #pragma unroll
                for (int nb = 0; nb < 8; nb++) {
                    mma16816(acc[mt][nb], ah, bh[nb]);
                    mma16816(acc[mt][nb], ah, bl[nb]);
                    mma16816(acc[mt][nb], al, bh[nb]);
                }
            }
        }
        __syncthreads();
    }

    // ---- stage u tile (+ sape ext cols) in Us ----
    {
        float* Us = (float*)(smem + OFF_US);
        int r0 = wid*32 + (lane>>2);
        int c0 = (lane&3)*2;
        #pragma unroll
        for (int mt = 0; mt < 2; mt++) {
            #pragma unroll
            for (int nb = 0; nb < 8; nb++) {
                int rr = r0 + mt*16;
                int cc = nb*8 + c0;
                Us[rr*USP + cc]     = acc[mt][nb][0];
                Us[rr*USP + cc+1]   = acc[mt][nb][1];
                Us[(rr+8)*USP + cc]   = acc[mt][nb][2];
                Us[(rr+8)*USP + cc+1] = acc[mt][nb][3];
            }
        }
        #pragma unroll
        for (int s = 0; s < 8; s++) {
            int idx = tid + s*128;
            int jj = idx >> 3, dd = idx & 7;
            Us[jj*USP + 64 + dd] = sape[(m0+jj)*ND + dd];
        }
    }
    __syncthreads();

    // ---- gate: g = u@Wg + sape@Wsp + te; h = gl*sigm(gr) ----
    {
        float* Us = (float*)(smem + OFF_US);
        float* Hs = (float*)(smem + OFF_HS);
        const float* te = (const float*)(smem + OFF_TE);
        int tx = tid & 15;
        int ty = tid >> 4;
        float accL[16][4] = {}, accR[16][4] = {};
        const float* wg = Wg + l*NC*128;
        #pragma unroll 4
        for (int c = 0; c < NC; c++) {
            float4 wl = *(const float4*)(wg + c*128 + tx*4);
            float4 wr = *(const float4*)(wg + c*128 + 64 + tx*4);
            #pragma unroll
            for (int jj = 0; jj < 16; jj++) {
                float uv = Us[(ty*16+jj)*USP + c];
                accL[jj][0] += uv*wl.x; accL[jj][1] += uv*wl.y;
                accL[jj][2] += uv*wl.z; accL[jj][3] += uv*wl.w;
                accR[jj][0] += uv*wr.x; accR[jj][1] += uv*wr.y;
                accR[jj][2] += uv*wr.z; accR[jj][3] += uv*wr.w;
            }
        }
        const float* wsp = Wsp + l*ND*128;
        #pragma unroll
        for (int dd = 0; dd < ND; dd++) {
            float4 wl = *(const float4*)(wsp + dd*128 + tx*4);
            float4 wr = *(const float4*)(wsp + dd*128 + 64 + tx*4);
            #pragma unroll
            for (int jj = 0; jj < 16; jj++) {
                float uv = Us[(ty*16+jj)*USP + 64 + dd];
                accL[jj][0] += uv*wl.x; accL[jj][1] += uv*wl.y;
                accL[jj][2] += uv*wl.z; accL[jj][3] += uv*wl.w;
                accR[jj][0] += uv*wr.x; accR[jj][1] += uv*wr.y;
                accR[jj][2] += uv*wr.z; accR[jj][3] += uv*wr.w;
            }
        }
        float tel[4] = {te[tx*4], te[tx*4+1], te[tx*4+2], te[tx*4+3]};
        float ter[4] = {te[64+tx*4], te[64+tx*4+1], te[64+tx*4+2], te[64+tx*4+3]};
        #pragma unroll
        for (int jj = 0; jj < 16; jj++) {
            int j = ty*16 + jj;
            #pragma unroll
            for (int q = 0; q < 4; q++) {
                float hv = (accL[jj][q] + tel[q]) * sigm(accR[jj][q] + ter[q]);
                Hs[(tx*4+q)*HSP + j] = hv;
            }
        }
    }
    __syncthreads();
    // ---- coalesced transposed writeback ----
    {
        const float* Hs = (const float*)(smem + OFF_HS);
        #pragma unroll
        for (int s = 0; s < 16; s++) {
            int idx = tid + s*128;
            int r = idx >> 5, q4 = idx & 31;
            float4 v = *(const float4*)(Hs + r*HSP + q4*4);
            *(float4*)(hout + ((size_t)((b*NT+t)*NC + r))*NV + m0 + q4*4) = v;
        }
    }
}

// ---- GFS (time conv) + GLU1 -> skips ----
__global__ void __launch_bounds__(128) k_gfs(const float* __restrict__ fs_b,
                                             const float* __restrict__ g1b, int l) {
    const float* hcur = (l & 1) ? g_hTA : g_hTB;
    int b  = blockIdx.x >> 6;
    int v0 = (blockIdx.x & 63) << 3;
    __shared__ float hs[8][NN+4];
    __shared__ float red[2][NC][8];
    __shared__ float ysh[8][NC];
    __shared__ float zsh[8][2*NC];
    int tid = threadIdx.x;
    for (int idx = tid; idx < 8*NN; idx += 128) {
        int vv = idx & 7;
        int c  = (idx >> 3) & 63;
        int t  = idx >> 9;
        hs[vv][t*NC + c] = hcur[((size_t)((b*NT+t)*NC + c))*NV + v0 + vv];
    }
    __syncthreads();
    int oo = tid & 63, half = tid >> 6;
    const float* fwT = g_fswT + l*NN*NC;
    float part[8] = {};
    for (int c = half*32; c < half*32 + 32; c++) {
        #pragma unroll
        for (int t = 0; t < NT; t++) {
            float w = fwT[(c*NT + t)*NC + oo];
            #pragma unroll
            for (int vv = 0; vv < 8; vv++) part[vv] += hs[vv][t*NC + c]*w;
        }
    }
    #pragma unroll
    for (int vv = 0; vv < 8; vv++) red[half][oo][vv] = part[vv];
    __syncthreads();
    if (half == 0) {
        float fb = fs_b[l*NC + oo];
        #pragma unroll
        for (int vv = 0; vv < 8; vv++) ysh[vv][oo] = red[0][oo][vv] + red[1][oo][vv] + fb;
    }
    __syncthreads();
    const float* gT = g_g1wT + l*NC*2*NC;
    float zacc[8];
    float zb = g1b[l*2*NC + tid];
    #pragma unroll
    for (int vv = 0; vv < 8; vv++) zacc[vv] = zb;
    for (int c = 0; c < NC; c++) {
        float w = gT[c*128 + tid];
        #pragma unroll
        for (int vv = 0; vv < 8; vv++) zacc[vv] += ysh[vv][c]*w;
    }
    #pragma unroll
    for (int vv = 0; vv < 8; vv++) zsh[vv][tid] = zacc[vv];
    __syncthreads();
    if (tid < NC) {
        #pragma unroll
        for (int vv = 0; vv < 8; vv++) {
            float zl = zsh[vv][tid], zr = zsh[vv][tid+NC];
            g_skips[(size_t)(b*NV + v0+vv)*256 + l*NC + tid] = zl * sigm(zr);
        }
    }
}

// ---- output GLU + head ----
__global__ void __launch_bounds__(256) k_out(const float* __restrict__ gout_b,
                                             const float* __restrict__ out_b,
                                             float* __restrict__ out) {
    int b  = blockIdx.x >> 5;
    int v0 = (blockIdx.x & 31) << 4;
    __shared__ float sin_[256][16];
    __shared__ float ssh[256][16];
    int tid = threadIdx.x;
    for (int idx = tid; idx < 256*16; idx += 256) {
        int vv = idx >> 8, ch = idx & 255;
        sin_[ch][vv] = g_skips[(size_t)(b*NV + v0+vv)*256 + ch];
    }
    __syncthreads();
    int o = tid;
    float a0[16] = {}, a1[16] = {};
    for (int c = 0; c < 256; c++) {
        float w0 = g_goutT[c*512 + o];
        float w1 = g_goutT[c*512 + o + 256];
        #pragma unroll
        for (int vv = 0; vv < 16; vv++) {
            float s = sin_[c][vv];
            a0[vv] += w0*s; a1[vv] += w1*s;
        }
    }
    float b0 = gout_b[o], b1 = gout_b[o+256];
    #pragma unroll
    for (int vv = 0; vv < 16; vv++) ssh[o][vv] = (a0[vv]+b0) * sigm(a1[vv]+b1);
    __syncthreads();
    if (tid < NP*16) {
        int p = tid >> 4, vv = tid & 15;
        float a = out_b[p];
        for (int c = 0; c < 256; c++) a += ssh[c][vv]*g_outT[c*NP + p];
        out[(b*NP + p)*NV + v0 + vv] = a;
    }
}

extern "C" void kernel_launch(void* const* d_in, const int* in_sizes, int n_in,
                              void* d_out, int out_size) {
    const float* x      = (const float*)d_in[0];
    const float* sape   = (const float*)d_in[1];
    const float* tape   = (const float*)d_in[2];
    const float* srpe   = (const float*)d_in[3];
    const float* trpe   = (const float*)d_in[4];
    const float* mask   = (const float*)d_in[7];
    const float* Wi     = (const float*)d_in[8];
    const float* bi     = (const float*)d_in[9];
    const float* gc_mu  = (const float*)d_in[10];
    const float* gc_sig = (const float*)d_in[11];
    const float* Wg     = (const float*)d_in[12];
    const float* bg     = (const float*)d_in[13];
    const float* Wsp    = (const float*)d_in[14];
    const float* Wtp    = (const float*)d_in[15];
    const float* fs_w   = (const float*)d_in[16];
    const float* fs_b   = (const float*)d_in[17];
    const float* g1w    = (const float*)d_in[18];
    const float* g1b    = (const float*)d_in[19];
    const float* goutw  = (const float*)d_in[20];
    const float* goutb  = (const float*)d_in[21];
    const float* outw   = (const float*)d_in[22];
    const float* outb   = (const float*)d_in[23];
    float* out = (float*)d_out;

    cudaFuncSetAttribute(k_gconv_mma, cudaFuncAttributeMaxDynamicSharedMemorySize, SMEM_TOTAL);

    k_transw<<<1420, 256>>>(fs_w, g1w, goutw, outw);
    k_input<<<6144, 256>>>(x, Wi, bi);
    k_prep<<<NL, 512>>>(sape, tape, trpe, gc_mu, gc_sig);
    k_ebase<<<dim3(1024, NL), 256>>>(srpe, gc_mu, gc_sig);
    k_asplit<<<12288, 256>>>(mask);
    for (int l = 0; l < NL; l++) {
        dim3 gg(NT, NV/128, NB);   // (12, 4, 4) = 192 CTAs
        k_gconv_mma<<<gg, 128, SMEM_TOTAL>>>(sape, tape, Wg, bg, Wsp, Wtp, l);
        k_gfs<<<NB*NV/8, 128>>>(fs_b, g1b, l);
    }
    k_out<<<NB*NV/16, 256>>>(goutb, outb, out);
}